// round 1
// baseline (speedup 1.0000x reference)
#include <cuda_runtime.h>

#define DD   64
#define GSZ  (DD*DD*DD)   // 262144
#define NMAX 65536
#define CC   32
#define FULLMASK 0xffffffffu

// ---------------- device scratch (no allocations allowed) ----------------
__device__ int   g_is64;
__device__ int   g_grid[GSZ];          // cell -> point index or -1
__device__ int   g_coords[NMAX];       // packed (z<<12)|(y<<6)|x
__device__ int   g_nbr[27 * NMAX];     // planar: [slot][point], packed (src<<5)|tap, or -1
__device__ float g_h1[NMAX * CC];      // intermediate features after layer 1

// ---------------- detect int64 vs int32 indices ----------------
// int64 layout: words [b_lo,b_hi,z_lo,z_hi,...] -> odd words all zero (coords < 2^31).
// int32 layout: odd words are z,x,... -> essentially never all zero over 256 samples.
__global__ void k_detect(const int* __restrict__ idx32) {
    int v = idx32[2 * threadIdx.x + 1];
    int any = __syncthreads_count(v != 0);
    if (threadIdx.x == 0) g_is64 = (any == 0) ? 1 : 0;
}

__global__ void k_init_grid() {
    int i = blockIdx.x * blockDim.x + threadIdx.x;
    if (i < GSZ) g_grid[i] = -1;
}

__global__ void k_fill(const void* __restrict__ idx, int N) {
    int m = blockIdx.x * blockDim.x + threadIdx.x;
    if (m >= N) return;
    int z, y, x;
    if (g_is64) {
        const long long* p = (const long long*)idx;
        z = (int)p[m * 4 + 1]; y = (int)p[m * 4 + 2]; x = (int)p[m * 4 + 3];
    } else {
        const int* p = (const int*)idx;
        z = p[m * 4 + 1]; y = p[m * 4 + 2]; x = p[m * 4 + 3];
    }
    int cp = (z << 12) | (y << 6) | x;
    g_coords[m] = cp;
    g_grid[cp] = m;
}

// Build 27 (tap, source) pairs per point. Per axis exactly 3 entries
// (clip-folding at boundaries preserved exactly).
__global__ void k_nbr(int N) {
    int m = blockIdx.x * blockDim.x + threadIdx.x;
    if (m >= N) return;
    int cp = g_coords[m];
    int vv[3] = { (cp >> 12) & 63, (cp >> 6) & 63, cp & 63 };
    int ti[3][3], sv[3][3];
#pragma unroll
    for (int a = 0; a < 3; a++) {
        int v = vv[a];
        if (v == 0) {
            ti[a][0] = 0; sv[a][0] = 0;
            ti[a][1] = 0; sv[a][1] = 1;
            ti[a][2] = 1; sv[a][2] = 0;
        } else if (v == DD - 1) {
            ti[a][0] = 2; sv[a][0] = DD - 2;
            ti[a][1] = 2; sv[a][1] = DD - 1;
            ti[a][2] = 1; sv[a][2] = DD - 1;
        } else {
            ti[a][0] = 0; sv[a][0] = v + 1;   // off=-1 -> src = v+1, tap component 0
            ti[a][1] = 1; sv[a][1] = v;       // off= 0
            ti[a][2] = 2; sv[a][2] = v - 1;   // off=+1
        }
    }
    int slot = 0;
#pragma unroll
    for (int a = 0; a < 3; a++)
#pragma unroll
        for (int b = 0; b < 3; b++)
#pragma unroll
            for (int c = 0; c < 3; c++) {
                int t   = ti[0][a] * 9 + ti[1][b] * 3 + ti[2][c];
                int lin = (sv[0][a] << 12) | (sv[1][b] << 6) | sv[2][c];
                int src = g_grid[lin];
                g_nbr[slot * NMAX + m] = (src < 0) ? -1 : ((src << 5) | t);
                slot++;
            }
}

// ---------------- conv kernel ----------------
// One warp processes 8 points; lane = output channel. Full 27x32x32 kernel in SMEM.
#define CONV_THREADS 512
#define CONV_WARPS   (CONV_THREADS / 32)
#define KERN_FLOATS  (27 * CC * CC)   // 27648

__global__ __launch_bounds__(CONV_THREADS, 1)
void k_conv(const float* __restrict__ in_feat,
            const float* __restrict__ kern,
            const float* __restrict__ bias,
            const float* __restrict__ mask,
            const float* __restrict__ resid,   // may be null
            float* __restrict__ out_feat,
            int N, int do_relu)
{
    extern __shared__ float s[];
    // load full kernel into smem
    for (int i = threadIdx.x; i < KERN_FLOATS; i += blockDim.x)
        s[i] = kern[i];
    float* stage = s + KERN_FLOATS + (threadIdx.x >> 5) * (8 * CC);
    __syncthreads();

    int lane   = threadIdx.x & 31;
    int warp   = blockIdx.x * CONV_WARPS + (threadIdx.x >> 5);
    int nwarp  = gridDim.x * CONV_WARPS;
    int ngroup = (N + 7) >> 3;
    float bv = bias[lane];

    for (int g = warp; g < ngroup; g += nwarp) {
        int base = g * 8;
        float acc[8];
#pragma unroll
        for (int j = 0; j < 8; j++) acc[j] = 0.f;

        for (int slot = 0; slot < 27; slot++) {
            int packed = -1;
            if (lane < 8 && (base + lane) < N)
                packed = g_nbr[slot * NMAX + base + lane];

            unsigned okb = __ballot_sync(FULLMASK,
                (lane >= 8) || packed < 0 || (packed & 31) == slot);
            bool uniform = (okb == FULLMASK);

            // gather 8 source feature vectors into staging
#pragma unroll
            for (int j = 0; j < 8; j++) {
                int pk = __shfl_sync(FULLMASK, packed, j);
                float v = 0.f;
                if (pk >= 0) v = in_feat[(pk >> 5) * CC + lane];
                stage[j * CC + lane] = v;
            }
            __syncwarp();

            if (uniform) {
                const float* Wt = s + slot * (CC * CC);
#pragma unroll
                for (int c4 = 0; c4 < 8; c4++) {
                    float w0 = Wt[(c4 * 4 + 0) * CC + lane];
                    float w1 = Wt[(c4 * 4 + 1) * CC + lane];
                    float w2 = Wt[(c4 * 4 + 2) * CC + lane];
                    float w3 = Wt[(c4 * 4 + 3) * CC + lane];
#pragma unroll
                    for (int j = 0; j < 8; j++) {
                        float4 f = *(const float4*)&stage[j * CC + c4 * 4];
                        acc[j] = fmaf(f.x, w0, acc[j]);
                        acc[j] = fmaf(f.y, w1, acc[j]);
                        acc[j] = fmaf(f.z, w2, acc[j]);
                        acc[j] = fmaf(f.w, w3, acc[j]);
                    }
                }
            } else {
#pragma unroll
                for (int j = 0; j < 8; j++) {
                    int pk = __shfl_sync(FULLMASK, packed, j);
                    if (pk < 0) continue;
                    const float* Wt = s + (pk & 31) * (CC * CC);
#pragma unroll
                    for (int c4 = 0; c4 < 8; c4++) {
                        float4 f = *(const float4*)&stage[j * CC + c4 * 4];
                        acc[j] = fmaf(f.x, Wt[(c4 * 4 + 0) * CC + lane], acc[j]);
                        acc[j] = fmaf(f.y, Wt[(c4 * 4 + 1) * CC + lane], acc[j]);
                        acc[j] = fmaf(f.z, Wt[(c4 * 4 + 2) * CC + lane], acc[j]);
                        acc[j] = fmaf(f.w, Wt[(c4 * 4 + 3) * CC + lane], acc[j]);
                    }
                }
            }
            __syncwarp();
        }

        // epilogue: out = (acc + mask*bias) * mask [+relu] [+resid]
#pragma unroll
        for (int j = 0; j < 8; j++) {
            int m = base + j;
            if (m < N) {
                float mk = mask[m];
                float o = (acc[j] + mk * bv) * mk;
                if (do_relu) o = fmaxf(o, 0.f);
                if (resid) o += resid[m * CC + lane];
                out_feat[m * CC + lane] = o;
            }
        }
    }
}

// ---------------- launch ----------------
extern "C" void kernel_launch(void* const* d_in, const int* in_sizes, int n_in,
                              void* d_out, int out_size)
{
    const float* values = (const float*)d_in[0];
    const void*  indices = d_in[1];
    const float* mask   = (const float*)d_in[2];
    const float* kern1  = (const float*)d_in[3];
    const float* bias1  = (const float*)d_in[4];
    const float* kern2  = (const float*)d_in[5];
    const float* bias2  = (const float*)d_in[6];
    float* out = (float*)d_out;

    int N = in_sizes[0] / CC;
    if (N > NMAX) N = NMAX;

    static int smem_set = 0;
    int smem = KERN_FLOATS * 4 + CONV_WARPS * 8 * CC * 4;   // 110592 + 16384
    if (!smem_set) {
        cudaFuncSetAttribute(k_conv, cudaFuncAttributeMaxDynamicSharedMemorySize, smem);
        smem_set = 1;
    }

    float* h1;
    cudaGetSymbolAddress((void**)&h1, g_h1);

    k_detect<<<1, 256>>>((const int*)indices);
    k_init_grid<<<(GSZ + 1023) / 1024, 1024>>>();
    k_fill<<<(N + 255) / 256, 256>>>(indices, N);
    k_nbr<<<(N + 255) / 256, 256>>>(N);

    k_conv<<<148, CONV_THREADS, smem>>>(values, kern1, bias1, mask, nullptr, h1, N, 1);
    k_conv<<<148, CONV_THREADS, smem>>>(h1, kern2, bias2, mask, values, out, N, 0);
}

// round 2
// speedup vs baseline: 1.0608x; 1.0608x over previous
#include <cuda_runtime.h>

#define DD   64
#define GSZ  (DD*DD*DD)   // 262144
#define NMAX 65536
#define CC   32
#define FULLMASK 0xffffffffu

// ---------------- device scratch (no allocations allowed) ----------------
__device__ int   g_is64;
__device__ int   g_grid[GSZ];          // cell -> point index or -1
__device__ int   g_coords[NMAX];       // packed (z<<12)|(y<<6)|x
__device__ int   g_nbr[27 * NMAX];     // planar: [slot][point], packed (src<<5)|tap, or -1
__device__ float g_h1[NMAX * CC];      // intermediate features after layer 1

// ---------------- f32x2 packed math helpers ----------------
__device__ __forceinline__ unsigned long long fma2(unsigned long long a,
                                                   unsigned long long b,
                                                   unsigned long long c) {
    unsigned long long d;
    asm("fma.rn.f32x2 %0, %1, %2, %3;" : "=l"(d) : "l"(a), "l"(b), "l"(c));
    return d;
}
__device__ __forceinline__ unsigned long long pack2(float lo, float hi) {
    unsigned long long d;
    asm("mov.b64 %0, {%1, %2};" : "=l"(d) : "f"(lo), "f"(hi));
    return d;
}
__device__ __forceinline__ float hsum2(unsigned long long a) {
    float lo, hi;
    asm("mov.b64 {%0, %1}, %2;" : "=f"(lo), "=f"(hi) : "l"(a));
    return lo + hi;
}

// ---------------- pre: grid init + int64/int32 detection ----------------
// int64 layout: words [b_lo,b_hi,z_lo,z_hi,...] -> odd words all zero.
__global__ void k_pre(const int* __restrict__ idx32) {
    int i = blockIdx.x * blockDim.x + threadIdx.x;
    if (i < GSZ) g_grid[i] = -1;
    if (blockIdx.x == 0) {
        int v = 0;
        if (threadIdx.x < 256) v = idx32[2 * threadIdx.x + 1];
        int any = __syncthreads_count(v != 0);
        if (threadIdx.x == 0) g_is64 = (any == 0) ? 1 : 0;
    }
}

__global__ void k_fill(const void* __restrict__ idx, int N) {
    int m = blockIdx.x * blockDim.x + threadIdx.x;
    if (m >= N) return;
    int z, y, x;
    if (g_is64) {
        const long long* p = (const long long*)idx;
        z = (int)p[m * 4 + 1]; y = (int)p[m * 4 + 2]; x = (int)p[m * 4 + 3];
    } else {
        const int* p = (const int*)idx;
        z = p[m * 4 + 1]; y = p[m * 4 + 2]; x = p[m * 4 + 3];
    }
    int cp = (z << 12) | (y << 6) | x;
    g_coords[m] = cp;
    g_grid[cp] = m;
}

// Build 27 (tap, source) pairs per point (exact inverse of scatter-with-clip).
__global__ void k_nbr(int N) {
    int m = blockIdx.x * blockDim.x + threadIdx.x;
    if (m >= N) return;
    int cp = g_coords[m];
    int vv[3] = { (cp >> 12) & 63, (cp >> 6) & 63, cp & 63 };
    int ti[3][3], sv[3][3];
#pragma unroll
    for (int a = 0; a < 3; a++) {
        int v = vv[a];
        if (v == 0) {
            ti[a][0] = 0; sv[a][0] = 0;
            ti[a][1] = 0; sv[a][1] = 1;
            ti[a][2] = 1; sv[a][2] = 0;
        } else if (v == DD - 1) {
            ti[a][0] = 2; sv[a][0] = DD - 2;
            ti[a][1] = 2; sv[a][1] = DD - 1;
            ti[a][2] = 1; sv[a][2] = DD - 1;
        } else {
            ti[a][0] = 0; sv[a][0] = v + 1;
            ti[a][1] = 1; sv[a][1] = v;
            ti[a][2] = 2; sv[a][2] = v - 1;
        }
    }
    int slot = 0;
#pragma unroll
    for (int a = 0; a < 3; a++)
#pragma unroll
        for (int b = 0; b < 3; b++)
#pragma unroll
            for (int c = 0; c < 3; c++) {
                int t   = ti[0][a] * 9 + ti[1][b] * 3 + ti[2][c];
                int lin = (sv[0][a] << 12) | (sv[1][b] << 6) | sv[2][c];
                int src = g_grid[lin];
                g_nbr[slot * NMAX + m] = (src < 0) ? -1 : ((src << 5) | t);
                slot++;
            }
}

// ---------------- conv kernel ----------------
// One warp = 8 points, lane = c_out. Full 27x32x32 weights in SMEM.
// Math in packed f32x2: even c_in accumulates in .lo, odd c_in in .hi,
// horizontal add at the end. Feature pairs come free from LDS.128 (double2).
#define CONV_THREADS 512
#define CONV_WARPS   (CONV_THREADS / 32)
#define KERN_FLOATS  (27 * CC * CC)   // 27648

__global__ __launch_bounds__(CONV_THREADS, 1)
void k_conv(const float* __restrict__ in_feat,
            const float* __restrict__ kern,
            const float* __restrict__ bias,
            const float* __restrict__ mask,
            const float* __restrict__ resid,   // may be null
            float* __restrict__ out_feat,
            int N, int do_relu)
{
    extern __shared__ float s[];
    for (int i = threadIdx.x; i < KERN_FLOATS; i += blockDim.x)
        s[i] = kern[i];
    float* stage = s + KERN_FLOATS + (threadIdx.x >> 5) * (8 * CC);
    __syncthreads();

    int lane   = threadIdx.x & 31;
    int warp   = blockIdx.x * CONV_WARPS + (threadIdx.x >> 5);
    int nwarp  = gridDim.x * CONV_WARPS;
    int ngroup = (N + 7) >> 3;
    float bv = bias[lane];

    for (int g = warp; g < ngroup; g += nwarp) {
        int base = g * 8;
        bool act = (lane < 8) && (base + lane < N);

        unsigned long long acc2[8];
#pragma unroll
        for (int j = 0; j < 8; j++) acc2[j] = 0ull;

        // prefetch slot 0's packed indices
        int packed = -1;
        if (act) packed = g_nbr[0 * NMAX + base + lane];

        for (int slot = 0; slot < 27; slot++) {
            // prefetch next slot early (hides LDG latency behind this slot's math)
            int packed_next = -1;
            if (slot < 26 && act) packed_next = g_nbr[(slot + 1) * NMAX + base + lane];

            unsigned okb = __ballot_sync(FULLMASK,
                (lane >= 8) || packed < 0 || (packed & 31) == slot);
            bool uniform = (okb == FULLMASK);

            // gather 8 source feature vectors into staging (coalesced rows)
#pragma unroll
            for (int j = 0; j < 8; j++) {
                int pk = __shfl_sync(FULLMASK, packed, j);
                float v = 0.f;
                if (pk >= 0) v = in_feat[(pk >> 5) * CC + lane];
                stage[j * CC + lane] = v;
            }
            __syncwarp();

            if (uniform) {
                const float* Wt = s + slot * (CC * CC);
#pragma unroll
                for (int c4 = 0; c4 < 8; c4++) {
                    float w0 = Wt[(c4 * 4 + 0) * CC + lane];
                    float w1 = Wt[(c4 * 4 + 1) * CC + lane];
                    float w2 = Wt[(c4 * 4 + 2) * CC + lane];
                    float w3 = Wt[(c4 * 4 + 3) * CC + lane];
                    unsigned long long wp0 = pack2(w0, w1);
                    unsigned long long wp1 = pack2(w2, w3);
#pragma unroll
                    for (int j = 0; j < 8; j++) {
                        double2 f = *(const double2*)&stage[j * CC + c4 * 4];
                        acc2[j] = fma2(__double_as_longlong(f.x), wp0, acc2[j]);
                        acc2[j] = fma2(__double_as_longlong(f.y), wp1, acc2[j]);
                    }
                }
            } else {
#pragma unroll
                for (int j = 0; j < 8; j++) {
                    int pk = __shfl_sync(FULLMASK, packed, j);
                    if (pk < 0) continue;
                    const float* Wt = s + (pk & 31) * (CC * CC);
                    unsigned long long a = acc2[j];
#pragma unroll
                    for (int c4 = 0; c4 < 8; c4++) {
                        unsigned long long wp0 = pack2(Wt[(c4 * 4 + 0) * CC + lane],
                                                       Wt[(c4 * 4 + 1) * CC + lane]);
                        unsigned long long wp1 = pack2(Wt[(c4 * 4 + 2) * CC + lane],
                                                       Wt[(c4 * 4 + 3) * CC + lane]);
                        double2 f = *(const double2*)&stage[j * CC + c4 * 4];
                        a = fma2(__double_as_longlong(f.x), wp0, a);
                        a = fma2(__double_as_longlong(f.y), wp1, a);
                    }
                    acc2[j] = a;
                }
            }
            __syncwarp();
            packed = packed_next;
        }

        // epilogue: out = (sum + mask*bias) * mask [+relu] [+resid]
#pragma unroll
        for (int j = 0; j < 8; j++) {
            int m = base + j;
            if (m < N) {
                float mk = mask[m];
                float o = (hsum2(acc2[j]) + mk * bv) * mk;
                if (do_relu) o = fmaxf(o, 0.f);
                if (resid) o += resid[m * CC + lane];
                out_feat[m * CC + lane] = o;
            }
        }
    }
}

// ---------------- launch ----------------
extern "C" void kernel_launch(void* const* d_in, const int* in_sizes, int n_in,
                              void* d_out, int out_size)
{
    const float* values = (const float*)d_in[0];
    const void*  indices = d_in[1];
    const float* mask   = (const float*)d_in[2];
    const float* kern1  = (const float*)d_in[3];
    const float* bias1  = (const float*)d_in[4];
    const float* kern2  = (const float*)d_in[5];
    const float* bias2  = (const float*)d_in[6];
    float* out = (float*)d_out;

    int N = in_sizes[0] / CC;
    if (N > NMAX) N = NMAX;

    static int smem_set = 0;
    int smem = KERN_FLOATS * 4 + CONV_WARPS * 8 * CC * 4;   // 110592 + 16384
    if (!smem_set) {
        cudaFuncSetAttribute(k_conv, cudaFuncAttributeMaxDynamicSharedMemorySize, smem);
        smem_set = 1;
    }

    float* h1;
    cudaGetSymbolAddress((void**)&h1, g_h1);

    k_pre<<<(GSZ + 1023) / 1024, 1024>>>((const int*)indices);
    k_fill<<<(N + 255) / 256, 256>>>(indices, N);
    k_nbr<<<(N + 255) / 256, 256>>>(N);

    k_conv<<<148, CONV_THREADS, smem>>>(values, kern1, bias1, mask, nullptr, h1, N, 1);
    k_conv<<<148, CONV_THREADS, smem>>>(h1, kern2, bias2, mask, values, out, N, 0);
}

// round 3
// speedup vs baseline: 1.1132x; 1.0494x over previous
#include <cuda_runtime.h>

#define DD   64
#define GSZ  (DD*DD*DD)
#define NMAX 65536
#define CC   32
#define PITCH 36            // stage row pitch in floats ([point][cin])
#define FULLMASK 0xffffffffu

// ---------------- device scratch ----------------
__device__ int   g_is64;
__device__ int   g_grid[GSZ];
__device__ int   g_coords[NMAX];
__device__ int   g_nbr[27 * NMAX];   // planar [slot][pos], packed (src<<5)|tap, or -1
__device__ int   g_perm[NMAX];       // pos -> original point id (interior first)
__device__ int   g_cnt_i;
__device__ int   g_cnt_b;
__device__ float g_h1[NMAX * CC];

// ---------------- f32x2 helpers ----------------
__device__ __forceinline__ unsigned long long fma2(unsigned long long a,
                                                   unsigned long long b,
                                                   unsigned long long c) {
    unsigned long long d;
    asm("fma.rn.f32x2 %0, %1, %2, %3;" : "=l"(d) : "l"(a), "l"(b), "l"(c));
    return d;
}
__device__ __forceinline__ float hsum2(unsigned long long a) {
    float lo, hi;
    asm("mov.b64 {%0, %1}, %2;" : "=f"(lo), "=f"(hi) : "l"(a));
    return lo + hi;
}
__device__ __forceinline__ unsigned long long ldsd(const float* p) {
    return __double_as_longlong(*(const double*)p);
}

// ---------------- pre: grid init + counters + int64 detection ----------------
__global__ void k_pre(const int* __restrict__ idx32) {
    int i = blockIdx.x * blockDim.x + threadIdx.x;
    if (i < GSZ) g_grid[i] = -1;
    if (blockIdx.x == 0) {
        if (threadIdx.x == 0) { g_cnt_i = 0; g_cnt_b = 0; }
        int v = 0;
        if (threadIdx.x < 256) v = idx32[2 * threadIdx.x + 1];
        int any = __syncthreads_count(v != 0);
        if (threadIdx.x == 0) g_is64 = (any == 0) ? 1 : 0;
    }
}

__global__ void k_fill(const void* __restrict__ idx, int N) {
    int m = blockIdx.x * blockDim.x + threadIdx.x;
    if (m >= N) return;
    int z, y, x;
    if (g_is64) {
        const long long* p = (const long long*)idx;
        z = (int)p[m * 4 + 1]; y = (int)p[m * 4 + 2]; x = (int)p[m * 4 + 3];
    } else {
        const int* p = (const int*)idx;
        z = p[m * 4 + 1]; y = p[m * 4 + 2]; x = p[m * 4 + 3];
    }
    int cp = (z << 12) | (y << 6) | x;
    g_coords[m] = cp;
    g_grid[cp] = m;
}

// neighbors + interior/boundary partition
__global__ void k_nbr(int N) {
    int m = blockIdx.x * blockDim.x + threadIdx.x;
    if (m >= N) return;
    int cp = g_coords[m];
    int vv[3] = { (cp >> 12) & 63, (cp >> 6) & 63, cp & 63 };
    bool interior = true;
    int ti[3][3], sv[3][3];
#pragma unroll
    for (int a = 0; a < 3; a++) {
        int v = vv[a];
        if (v == 0) {
            interior = false;
            ti[a][0] = 0; sv[a][0] = 0;
            ti[a][1] = 0; sv[a][1] = 1;
            ti[a][2] = 1; sv[a][2] = 0;
        } else if (v == DD - 1) {
            interior = false;
            ti[a][0] = 2; sv[a][0] = DD - 2;
            ti[a][1] = 2; sv[a][1] = DD - 1;
            ti[a][2] = 1; sv[a][2] = DD - 1;
        } else {
            ti[a][0] = 0; sv[a][0] = v + 1;
            ti[a][1] = 1; sv[a][1] = v;
            ti[a][2] = 2; sv[a][2] = v - 1;
        }
    }
    int pos;
    if (interior) pos = atomicAdd(&g_cnt_i, 1);
    else          pos = N - 1 - atomicAdd(&g_cnt_b, 1);
    g_perm[pos] = m;

    int slot = 0;
#pragma unroll
    for (int a = 0; a < 3; a++)
#pragma unroll
        for (int b = 0; b < 3; b++)
#pragma unroll
            for (int c = 0; c < 3; c++) {
                int t   = ti[0][a] * 9 + ti[1][b] * 3 + ti[2][c];
                int lin = (sv[0][a] << 12) | (sv[1][b] << 6) | sv[2][c];
                int src = g_grid[lin];
                g_nbr[slot * NMAX + pos] = (src < 0) ? -1 : ((src << 5) | t);
                slot++;
            }
}

// ---------------- conv kernel ----------------
#define CONV_THREADS 512
#define CONV_WARPS   16
#define WFLOATS      (27 * 1024)
#define STAGE_FLOATS (32 * PITCH)

__global__ __launch_bounds__(CONV_THREADS, 1)
void k_conv(const float* __restrict__ in_feat,
            const float* __restrict__ kern,
            const float* __restrict__ bias,
            const float* __restrict__ mask,
            const float* __restrict__ resid,
            float* __restrict__ out_feat,
            int N, int do_relu)
{
    extern __shared__ float s[];
    float* sw = s;
    // interleave weights: (t, ci, co) -> t*1024 + (ci>>1)*64 + ((co>>1)&3)*16 + (co>>3)*4 + (co&1)*2 + (ci&1)
    for (int i = threadIdx.x; i < WFLOATS; i += CONV_THREADS) {
        int t = i >> 10, r = i & 1023;
        int ci = r >> 5, co = r & 31;
        int dst = (t << 10) | ((ci >> 1) << 6) | (((co >> 1) & 3) << 4) | ((co >> 3) << 2) | ((co & 1) << 1) | (ci & 1);
        sw[dst] = kern[i];
    }
    __syncthreads();

    int lane = threadIdx.x & 31;
    int wloc = threadIdx.x >> 5;
    float* stage = s + WFLOATS + wloc * STAGE_FLOATS;
    int warp  = blockIdx.x * CONV_WARPS + wloc;
    int nwarp = gridDim.x * CONV_WARPS;

    int pg = lane >> 2;     // point group 0..7
    int cg = lane & 3;      // cout group 0..3

    int Ni = g_cnt_i;
    int GI = Ni >> 5;                       // full interior 32-tiles
    int slow_start = GI << 5;
    int GS = (N - slow_start + 7) >> 3;     // 8-pt slow tiles

    // biases for both paths
    float bvf[8];
#pragma unroll
    for (int j = 0; j < 8; j++) bvf[j] = bias[cg * 8 + j];
    float bvs = bias[lane];

    for (int w = warp; w < GI + GS; w += nwarp) {
        if (w < GI) {
            // ================= FAST PATH: 32 interior points =================
            int base = w << 5;
            unsigned long long acc[4][8];
#pragma unroll
            for (int k = 0; k < 4; k++)
#pragma unroll
                for (int j = 0; j < 8; j++) acc[k][j] = 0ull;

            int packed = g_nbr[base + lane];  // slot 0
            for (int slot = 0; slot < 27; slot++) {
                int pnext = (slot < 26) ? g_nbr[(slot + 1) * NMAX + base + lane] : 0;
                // gather 32 rows into stage [point][cin]
#pragma unroll
                for (int j = 0; j < 32; j++) {
                    int pk = __shfl_sync(FULLMASK, packed, j);
                    float f = 0.f;
                    if (pk >= 0) f = in_feat[(pk >> 5) * CC + lane];
                    stage[j * PITCH + lane] = f;
                }
                __syncwarp();

                const float* Wb = sw + (slot << 10);
#pragma unroll
                for (int cp = 0; cp < 16; cp++) {
                    const float* wr = Wb + cp * 64 + cg * 4;
                    double2 w0 = *(const double2*)(wr);
                    double2 w1 = *(const double2*)(wr + 16);
                    double2 w2 = *(const double2*)(wr + 32);
                    double2 w3 = *(const double2*)(wr + 48);
                    unsigned long long q0 = __double_as_longlong(w0.x);
                    unsigned long long q1 = __double_as_longlong(w0.y);
                    unsigned long long q2 = __double_as_longlong(w1.x);
                    unsigned long long q3 = __double_as_longlong(w1.y);
                    unsigned long long q4 = __double_as_longlong(w2.x);
                    unsigned long long q5 = __double_as_longlong(w2.y);
                    unsigned long long q6 = __double_as_longlong(w3.x);
                    unsigned long long q7 = __double_as_longlong(w3.y);
#pragma unroll
                    for (int k = 0; k < 4; k++) {
                        unsigned long long f2 = ldsd(stage + (pg + 8 * k) * PITCH + cp * 2);
                        acc[k][0] = fma2(f2, q0, acc[k][0]);
                        acc[k][1] = fma2(f2, q1, acc[k][1]);
                        acc[k][2] = fma2(f2, q2, acc[k][2]);
                        acc[k][3] = fma2(f2, q3, acc[k][3]);
                        acc[k][4] = fma2(f2, q4, acc[k][4]);
                        acc[k][5] = fma2(f2, q5, acc[k][5]);
                        acc[k][6] = fma2(f2, q6, acc[k][6]);
                        acc[k][7] = fma2(f2, q7, acc[k][7]);
                    }
                }
                __syncwarp();
                packed = pnext;
            }
            // epilogue
#pragma unroll
            for (int k = 0; k < 4; k++) {
                int orig = g_perm[base + pg + 8 * k];
                float mk = mask[orig];
                float o[8];
#pragma unroll
                for (int j = 0; j < 8; j++) {
                    float v = (hsum2(acc[k][j]) + mk * bvf[j]) * mk;
                    if (do_relu) v = fmaxf(v, 0.f);
                    o[j] = v;
                }
                float* op = out_feat + orig * CC + cg * 8;
                if (resid) {
                    const float* rp = resid + orig * CC + cg * 8;
                    float4 r0 = *(const float4*)rp;
                    float4 r1 = *(const float4*)(rp + 4);
                    o[0] += r0.x; o[1] += r0.y; o[2] += r0.z; o[3] += r0.w;
                    o[4] += r1.x; o[5] += r1.y; o[6] += r1.z; o[7] += r1.w;
                }
                *(float4*)op       = make_float4(o[0], o[1], o[2], o[3]);
                *(float4*)(op + 4) = make_float4(o[4], o[5], o[6], o[7]);
            }
        } else {
            // ================= SLOW PATH: 8 points, per-point taps =================
            int base = slow_start + ((w - GI) << 3);
            unsigned long long acc[8];
#pragma unroll
            for (int j = 0; j < 8; j++) acc[j] = 0ull;

            int packed = -1;
            if (lane < 8 && base + lane < N) packed = g_nbr[base + lane];
            for (int slot = 0; slot < 27; slot++) {
                int pnext = -1;
                if (slot < 26 && lane < 8 && base + lane < N)
                    pnext = g_nbr[(slot + 1) * NMAX + base + lane];
#pragma unroll
                for (int j = 0; j < 8; j++) {
                    int pk = __shfl_sync(FULLMASK, packed, j);
                    float f = 0.f;
                    if (pk >= 0) f = in_feat[(pk >> 5) * CC + lane];
                    stage[j * PITCH + lane] = f;
                }
                __syncwarp();
                // weight offset for co=lane: (q=(lane>>1)&3)*16 + (cg=lane>>3)*4 + (lane&1)*2
                int woff = (((lane >> 1) & 3) << 4) | ((lane >> 3) << 2) | ((lane & 1) << 1);
#pragma unroll
                for (int j = 0; j < 8; j++) {
                    int pk = __shfl_sync(FULLMASK, packed, j);
                    if (pk < 0) continue;
                    const float* Wb = sw + ((pk & 31) << 10) + woff;
                    unsigned long long a = acc[j];
#pragma unroll
                    for (int cpp = 0; cpp < 16; cpp++) {
                        unsigned long long f2 = ldsd(stage + j * PITCH + cpp * 2);
                        unsigned long long w2 = ldsd(Wb + cpp * 64);
                        a = fma2(f2, w2, a);
                    }
                    acc[j] = a;
                }
                __syncwarp();
                packed = pnext;
            }
#pragma unroll
            for (int j = 0; j < 8; j++) {
                int p = base + j;
                if (p < N) {
                    int orig = g_perm[p];
                    float mk = mask[orig];
                    float v = (hsum2(acc[j]) + mk * bvs) * mk;
                    if (do_relu) v = fmaxf(v, 0.f);
                    if (resid) v += resid[orig * CC + lane];
                    out_feat[orig * CC + lane] = v;
                }
            }
        }
    }
}

// ---------------- launch ----------------
extern "C" void kernel_launch(void* const* d_in, const int* in_sizes, int n_in,
                              void* d_out, int out_size)
{
    const float* values = (const float*)d_in[0];
    const void*  indices = d_in[1];
    const float* mask   = (const float*)d_in[2];
    const float* kern1  = (const float*)d_in[3];
    const float* bias1  = (const float*)d_in[4];
    const float* kern2  = (const float*)d_in[5];
    const float* bias2  = (const float*)d_in[6];
    float* out = (float*)d_out;

    int N = in_sizes[0] / CC;
    if (N > NMAX) N = NMAX;

    int smem = (WFLOATS + CONV_WARPS * STAGE_FLOATS) * 4;   // 110592 + 73728 = 184320
    static int smem_set = 0;
    if (!smem_set) {
        cudaFuncSetAttribute(k_conv, cudaFuncAttributeMaxDynamicSharedMemorySize, smem);
        smem_set = 1;
    }

    float* h1;
    cudaGetSymbolAddress((void**)&h1, g_h1);

    k_pre<<<(GSZ + 1023) / 1024, 1024>>>((const int*)indices);
    k_fill<<<(N + 255) / 256, 256>>>(indices, N);
    k_nbr<<<(N + 255) / 256, 256>>>(N);

    k_conv<<<148, CONV_THREADS, smem>>>(values, kern1, bias1, mask, nullptr, h1, N, 1);
    k_conv<<<148, CONV_THREADS, smem>>>(h1, kern2, bias2, mask, values, out, N, 0);
}

// round 4
// speedup vs baseline: 2.1895x; 1.9668x over previous
#include <cuda_runtime.h>

#define DD   64
#define GSZ  (DD*DD*DD)
#define NMAX 65536
#define CC   32
#define PITCH 36
#define FULLMASK 0xffffffffu
#define WFLOATS (27 * 1024)

// ---------------- device scratch ----------------
__device__ int   g_is64;
__device__ int   g_grid[GSZ];
__device__ int   g_coords[NMAX];
__device__ unsigned int g_pairs[27 * NMAX];  // bucket t at t*NMAX: (src<<16)|m
__device__ int   g_cnt[27 * 32];             // padded counters (128B apart)
__device__ int   g_tilebase[28];
__device__ float g_acc[NMAX * CC];
__device__ float g_h1[NMAX * CC];

// ---------------- f32x2 helpers ----------------
__device__ __forceinline__ unsigned long long fma2(unsigned long long a,
                                                   unsigned long long b,
                                                   unsigned long long c) {
    unsigned long long d;
    asm("fma.rn.f32x2 %0, %1, %2, %3;" : "=l"(d) : "l"(a), "l"(b), "l"(c));
    return d;
}
__device__ __forceinline__ float hsum2(unsigned long long a) {
    float lo, hi;
    asm("mov.b64 {%0, %1}, %2;" : "=f"(lo), "=f"(hi) : "l"(a));
    return lo + hi;
}
__device__ __forceinline__ void red2(float* p, float a, float b) {
    asm volatile("red.global.add.v2.f32 [%0], {%1, %2};" :: "l"(p), "f"(a), "f"(b) : "memory");
}

// ---------------- pre: init grid/acc/counters + dtype detection ----------------
__global__ void k_pre(const int* __restrict__ idx32) {
    int i = blockIdx.x * blockDim.x + threadIdx.x;   // 524288 threads
    if (i < GSZ) g_grid[i] = -1;
    ((float4*)g_acc)[i] = make_float4(0.f, 0.f, 0.f, 0.f);
    if (i < 27 * 32) g_cnt[i] = 0;
    if (blockIdx.x == 0) {
        int v = (threadIdx.x < 256) ? idx32[2 * threadIdx.x + 1] : 0;
        int any = __syncthreads_count(v != 0);
        if (threadIdx.x == 0) g_is64 = (any == 0) ? 1 : 0;
    }
}

__global__ void k_fill(const void* __restrict__ idx, int N) {
    int m = blockIdx.x * blockDim.x + threadIdx.x;
    if (m >= N) return;
    int z, y, x;
    if (g_is64) {
        const long long* p = (const long long*)idx;
        z = (int)p[m * 4 + 1]; y = (int)p[m * 4 + 2]; x = (int)p[m * 4 + 3];
    } else {
        const int* p = (const int*)idx;
        z = p[m * 4 + 1]; y = p[m * 4 + 2]; x = p[m * 4 + 3];
    }
    int cp = (z << 12) | (y << 6) | x;
    g_coords[m] = cp;
    g_grid[cp] = m;
}

// Enumerate present (tap, src) per point, bucket by tap.
// Interior points have tap==slot -> warp-ballot aggregated atomics.
__global__ void k_pairs(int N) {
    int m = blockIdx.x * blockDim.x + threadIdx.x;
    bool active = (m < N);
    int cp = active ? g_coords[m] : 0;
    int vv[3] = { (cp >> 12) & 63, (cp >> 6) & 63, cp & 63 };
    bool inter = true;
    int ti[3][3], sv[3][3];
#pragma unroll
    for (int a = 0; a < 3; a++) {
        int v = vv[a];
        if (v == 0) {
            inter = false;
            ti[a][0] = 0; sv[a][0] = 0;
            ti[a][1] = 0; sv[a][1] = 1;
            ti[a][2] = 1; sv[a][2] = 0;
        } else if (v == DD - 1) {
            inter = false;
            ti[a][0] = 2; sv[a][0] = DD - 2;
            ti[a][1] = 2; sv[a][1] = DD - 1;
            ti[a][2] = 1; sv[a][2] = DD - 1;
        } else {
            ti[a][0] = 0; sv[a][0] = v + 1;
            ti[a][1] = 1; sv[a][1] = v;
            ti[a][2] = 2; sv[a][2] = v - 1;
        }
    }
    int lane = threadIdx.x & 31;
    int slot = 0;
#pragma unroll
    for (int a = 0; a < 3; a++)
#pragma unroll
        for (int b = 0; b < 3; b++)
#pragma unroll
            for (int c = 0; c < 3; c++) {
                int t   = ti[0][a] * 9 + ti[1][b] * 3 + ti[2][c];
                int lin = (sv[0][a] << 12) | (sv[1][b] << 6) | sv[2][c];
                int src = active ? g_grid[lin] : -1;
                bool present = (src >= 0);
                bool fast = inter && present;   // here t == slot
                unsigned bal = __ballot_sync(FULLMASK, fast);
                int ldr = bal ? (__ffs(bal) - 1) : 0;
                int base = 0;
                if (bal && lane == ldr) base = atomicAdd(&g_cnt[slot * 32], __popc(bal));
                base = __shfl_sync(FULLMASK, base, ldr);
                int pos = 0;
                if (fast)          pos = base + __popc(bal & ((1u << lane) - 1u));
                else if (present)  pos = atomicAdd(&g_cnt[t * 32], 1);
                if (present) g_pairs[t * NMAX + pos] = ((unsigned)src << 16) | (unsigned)m;
                slot++;
            }
}

// tilebase prefix sum (one warp)
__global__ void k_tiles() {
    int lane = threadIdx.x;
    int c = (lane < 27) ? g_cnt[lane * 32] : 0;
    int tiles = (c + 31) >> 5;
    int incl = tiles;
#pragma unroll
    for (int o = 1; o < 32; o <<= 1) {
        int v = __shfl_up_sync(FULLMASK, incl, o);
        if (lane >= o) incl += v;
    }
    if (lane < 27) g_tilebase[lane] = incl - tiles;
    if (lane == 31) g_tilebase[27] = incl;
}

// ---------------- sparse tap-sorted conv ----------------
__global__ __launch_bounds__(512, 1)
void k_conv_s(const float* __restrict__ in_feat, const float* __restrict__ kern) {
    extern __shared__ float s[];
    int* s_tb  = (int*)s;        // 28
    int* s_cnt = s_tb + 28;      // 27
    float* sw  = s + 64;
    int tid = threadIdx.x;
    if (tid < 28) s_tb[tid] = g_tilebase[tid];
    else if (tid < 55) s_cnt[tid - 28] = g_cnt[(tid - 28) * 32];
    // interleave weights: (t,ci,co) -> t*1024 + (ci>>1)*64 + ((co>>1)&3)*16 + (co>>3)*4 + (co&1)*2 + (ci&1)
    for (int i = tid; i < WFLOATS; i += 512) {
        int t = i >> 10, r = i & 1023;
        int ci = r >> 5, co = r & 31;
        int dst = (t << 10) | ((ci >> 1) << 6) | (((co >> 1) & 3) << 4) | ((co >> 3) << 2) | ((co & 1) << 1) | (ci & 1);
        sw[dst] = kern[i];
    }
    __syncthreads();

    int lane = tid & 31;
    int wloc = tid >> 5;
    float* stage = s + 64 + WFLOATS + wloc * (32 * PITCH);
    int warp  = blockIdx.x * 16 + wloc;
    int nwarp = gridDim.x * 16;
    int total = s_tb[27];
    int pg = lane >> 2, cg = lane & 3;

    for (int T = warp; T < total; T += nwarp) {
        int t = 0;
#pragma unroll 1
        while (t < 26 && T >= s_tb[t + 1]) t++;
        int li  = T - s_tb[t];
        int cnt = s_cnt[t];
        int idx = (li << 5) + lane;
        unsigned pw = (idx < cnt) ? g_pairs[t * NMAX + idx] : 0u;

        // gather 32 rows (128B each) via LDG.128, 8 warp insts
#pragma unroll
        for (int i = 0; i < 8; i++) {
            unsigned pr = __shfl_sync(FULLMASK, pw, 4 * i + (lane >> 3));
            int srow = (int)(pr >> 16);
            float4 v = ((const float4*)(in_feat + (size_t)srow * CC))[lane & 7];
            *(float4*)(stage + (4 * i + (lane >> 3)) * PITCH + (lane & 7) * 4) = v;
        }
        __syncwarp();

        unsigned long long acc[4][8];
#pragma unroll
        for (int k = 0; k < 4; k++)
#pragma unroll
            for (int j = 0; j < 8; j++) acc[k][j] = 0ull;

        const float* Wb = sw + (t << 10);
#pragma unroll
        for (int cp2 = 0; cp2 < 8; cp2++) {
            unsigned long long fx[4], fy[4];
#pragma unroll
            for (int k = 0; k < 4; k++) {
                double2 f = *(const double2*)(stage + (pg + 8 * k) * PITCH + cp2 * 4);
                fx[k] = __double_as_longlong(f.x);
                fy[k] = __double_as_longlong(f.y);
            }
#pragma unroll
            for (int h = 0; h < 2; h++) {
                const float* wr = Wb + (2 * cp2 + h) * 64 + cg * 4;
                double2 w0 = *(const double2*)(wr);
                double2 w1 = *(const double2*)(wr + 16);
                double2 w2 = *(const double2*)(wr + 32);
                double2 w3 = *(const double2*)(wr + 48);
                unsigned long long q0 = __double_as_longlong(w0.x);
                unsigned long long q1 = __double_as_longlong(w0.y);
                unsigned long long q2 = __double_as_longlong(w1.x);
                unsigned long long q3 = __double_as_longlong(w1.y);
                unsigned long long q4 = __double_as_longlong(w2.x);
                unsigned long long q5 = __double_as_longlong(w2.y);
                unsigned long long q6 = __double_as_longlong(w3.x);
                unsigned long long q7 = __double_as_longlong(w3.y);
#pragma unroll
                for (int k = 0; k < 4; k++) {
                    unsigned long long f2 = h ? fy[k] : fx[k];
                    acc[k][0] = fma2(f2, q0, acc[k][0]);
                    acc[k][1] = fma2(f2, q1, acc[k][1]);
                    acc[k][2] = fma2(f2, q2, acc[k][2]);
                    acc[k][3] = fma2(f2, q3, acc[k][3]);
                    acc[k][4] = fma2(f2, q4, acc[k][4]);
                    acc[k][5] = fma2(f2, q5, acc[k][5]);
                    acc[k][6] = fma2(f2, q6, acc[k][6]);
                    acc[k][7] = fma2(f2, q7, acc[k][7]);
                }
            }
        }
        __syncwarp();   // stage reuse guard for next tile

        // scatter: predicated red.v2 atomics into g_acc
#pragma unroll
        for (int k = 0; k < 4; k++) {
            int j = pg + 8 * k;
            unsigned prj = __shfl_sync(FULLMASK, pw, j);
            bool v = ((li << 5) + j) < cnt;
            if (v) {
                unsigned mrow = prj & 0xffffu;
                float* p = g_acc + (size_t)mrow * CC + cg * 8;
                float o0 = hsum2(acc[k][0]), o1 = hsum2(acc[k][1]);
                float o2 = hsum2(acc[k][2]), o3 = hsum2(acc[k][3]);
                float o4 = hsum2(acc[k][4]), o5 = hsum2(acc[k][5]);
                float o6 = hsum2(acc[k][6]), o7 = hsum2(acc[k][7]);
                red2(p,     o0, o1);
                red2(p + 2, o2, o3);
                red2(p + 4, o4, o5);
                red2(p + 6, o6, o7);
            }
        }
    }
}

// ---------------- epilogue: (acc + mask*bias)*mask [+relu] [+resid], optional acc reset ----------------
__global__ void k_epi(const float* __restrict__ mask, const float* __restrict__ bias,
                      const float* __restrict__ resid, float* __restrict__ outp,
                      int N, int do_relu, int reset) {
    int i = blockIdx.x * blockDim.x + threadIdx.x;
    if (i >= N * 8) return;
    int m = i >> 3, q = i & 7;
    float4 a = ((float4*)g_acc)[i];
    float mk = mask[m];
    float4 b = ((const float4*)bias)[q];
    float4 o;
    o.x = (a.x + mk * b.x) * mk;
    o.y = (a.y + mk * b.y) * mk;
    o.z = (a.z + mk * b.z) * mk;
    o.w = (a.w + mk * b.w) * mk;
    if (do_relu) {
        o.x = fmaxf(o.x, 0.f); o.y = fmaxf(o.y, 0.f);
        o.z = fmaxf(o.z, 0.f); o.w = fmaxf(o.w, 0.f);
    }
    if (resid) {
        float4 r = ((const float4*)resid)[i];
        o.x += r.x; o.y += r.y; o.z += r.z; o.w += r.w;
    }
    ((float4*)outp)[i] = o;
    if (reset) ((float4*)g_acc)[i] = make_float4(0.f, 0.f, 0.f, 0.f);
}

// ---------------- launch ----------------
extern "C" void kernel_launch(void* const* d_in, const int* in_sizes, int n_in,
                              void* d_out, int out_size)
{
    const float* values = (const float*)d_in[0];
    const void*  indices = d_in[1];
    const float* mask   = (const float*)d_in[2];
    const float* kern1  = (const float*)d_in[3];
    const float* bias1  = (const float*)d_in[4];
    const float* kern2  = (const float*)d_in[5];
    const float* bias2  = (const float*)d_in[6];
    float* out = (float*)d_out;

    int N = in_sizes[0] / CC;
    if (N > NMAX) N = NMAX;

    int smem = (64 + WFLOATS + 16 * 32 * PITCH) * 4;   // 184576 B
    static int smem_set = 0;
    if (!smem_set) {
        cudaFuncSetAttribute(k_conv_s, cudaFuncAttributeMaxDynamicSharedMemorySize, smem);
        smem_set = 1;
    }

    float* h1;
    cudaGetSymbolAddress((void**)&h1, g_h1);

    k_pre<<<1024, 512>>>((const int*)indices);
    k_fill<<<(N + 255) / 256, 256>>>(indices, N);
    k_pairs<<<(N + 255) / 256, 256>>>(N);
    k_tiles<<<1, 32>>>();

    k_conv_s<<<148, 512, smem>>>(values, kern1);
    k_epi<<<(N * 8 + 511) / 512, 512>>>(mask, bias1, nullptr, h1, N, 1, 1);
    k_conv_s<<<148, 512, smem>>>(h1, kern2);
    k_epi<<<(N * 8 + 511) / 512, 512>>>(mask, bias2, values, out, N, 0, 0);
}

// round 5
// speedup vs baseline: 2.3109x; 1.0555x over previous
#include <cuda_runtime.h>

#define DD   64
#define GSZ  (DD*DD*DD)
#define NMAX 65536
#define CC   32
#define PITCH 36
#define FULLMASK 0xffffffffu
#define WFLOATS (27 * 1024)
#define CONV_WARPS 12
#define CONV_THREADS (CONV_WARPS * 32)

// ---------------- device scratch ----------------
__device__ int   g_is64;
__device__ int   g_done;
__device__ int   g_grid[GSZ];
__device__ int   g_coords[NMAX];
__device__ unsigned int g_pairs[27 * NMAX];  // bucket t at t*NMAX: (src<<16)|m
__device__ int   g_cnt[27 * 32];             // padded counters
__device__ int   g_tilebase[28];
__device__ float g_acc[NMAX * CC];
__device__ float g_h1[NMAX * CC];

// ---------------- f32x2 helpers ----------------
__device__ __forceinline__ unsigned long long fma2(unsigned long long a,
                                                   unsigned long long b,
                                                   unsigned long long c) {
    unsigned long long d;
    asm("fma.rn.f32x2 %0, %1, %2, %3;" : "=l"(d) : "l"(a), "l"(b), "l"(c));
    return d;
}
__device__ __forceinline__ float hsum2(unsigned long long a) {
    float lo, hi;
    asm("mov.b64 {%0, %1}, %2;" : "=f"(lo), "=f"(hi) : "l"(a));
    return lo + hi;
}
__device__ __forceinline__ void red2(float* p, float a, float b) {
    asm volatile("red.global.add.v2.f32 [%0], {%1, %2};" :: "l"(p), "f"(a), "f"(b) : "memory");
}

// ---------------- pre: init + dtype detection ----------------
__global__ void k_pre(const int* __restrict__ idx32) {
    int i = blockIdx.x * blockDim.x + threadIdx.x;   // 524288 threads
    if (i < GSZ) g_grid[i] = -1;
    ((float4*)g_acc)[i] = make_float4(0.f, 0.f, 0.f, 0.f);
    if (i < 27 * 32) g_cnt[i] = 0;
    if (i == 0) g_done = 0;
    if (blockIdx.x == 0) {
        int v = (threadIdx.x < 256) ? idx32[2 * threadIdx.x + 1] : 0;
        int any = __syncthreads_count(v != 0);
        if (threadIdx.x == 0) g_is64 = (any == 0) ? 1 : 0;
    }
}

__global__ void k_fill(const void* __restrict__ idx, int N) {
    int m = blockIdx.x * blockDim.x + threadIdx.x;
    if (m >= N) return;
    int z, y, x;
    if (g_is64) {
        const long long* p = (const long long*)idx;
        z = (int)p[m * 4 + 1]; y = (int)p[m * 4 + 2]; x = (int)p[m * 4 + 3];
    } else {
        const int* p = (const int*)idx;
        z = p[m * 4 + 1]; y = p[m * 4 + 2]; x = p[m * 4 + 3];
    }
    int cp = (z << 12) | (y << 6) | x;
    g_coords[m] = cp;
    g_grid[cp] = m;
}

// Enumerate present (tap, src) per point, bucket by tap; last block does prefix.
__global__ void k_pairs(int N) {
    int m = blockIdx.x * blockDim.x + threadIdx.x;
    bool active = (m < N);
    int cp = active ? g_coords[m] : 0;
    int vv[3] = { (cp >> 12) & 63, (cp >> 6) & 63, cp & 63 };
    bool inter = true;
    int ti[3][3], sv[3][3];
#pragma unroll
    for (int a = 0; a < 3; a++) {
        int v = vv[a];
        if (v == 0) {
            inter = false;
            ti[a][0] = 0; sv[a][0] = 0;
            ti[a][1] = 0; sv[a][1] = 1;
            ti[a][2] = 1; sv[a][2] = 0;
        } else if (v == DD - 1) {
            inter = false;
            ti[a][0] = 2; sv[a][0] = DD - 2;
            ti[a][1] = 2; sv[a][1] = DD - 1;
            ti[a][2] = 1; sv[a][2] = DD - 1;
        } else {
            ti[a][0] = 0; sv[a][0] = v + 1;
            ti[a][1] = 1; sv[a][1] = v;
            ti[a][2] = 2; sv[a][2] = v - 1;
        }
    }
    int lane = threadIdx.x & 31;
    int slot = 0;
#pragma unroll
    for (int a = 0; a < 3; a++)
#pragma unroll
        for (int b = 0; b < 3; b++)
#pragma unroll
            for (int c = 0; c < 3; c++) {
                int t   = ti[0][a] * 9 + ti[1][b] * 3 + ti[2][c];
                int lin = (sv[0][a] << 12) | (sv[1][b] << 6) | sv[2][c];
                int src = active ? g_grid[lin] : -1;
                bool present = (src >= 0);
                bool fast = inter && present;   // here t == slot
                unsigned bal = __ballot_sync(FULLMASK, fast);
                int ldr = bal ? (__ffs(bal) - 1) : 0;
                int base = 0;
                if (bal && lane == ldr) base = atomicAdd(&g_cnt[slot * 32], __popc(bal));
                base = __shfl_sync(FULLMASK, base, ldr);
                int pos = 0;
                if (fast)          pos = base + __popc(bal & ((1u << lane) - 1u));
                else if (present)  pos = atomicAdd(&g_cnt[t * 32], 1);
                if (present) g_pairs[t * NMAX + pos] = ((unsigned)src << 16) | (unsigned)m;
                slot++;
            }

    // fused prefix sum: last block to finish computes tile bases
    __shared__ int s_last;
    __threadfence();
    __syncthreads();
    if (threadIdx.x == 0)
        s_last = (atomicAdd(&g_done, 1) == (int)gridDim.x - 1) ? 1 : 0;
    __syncthreads();
    if (s_last && threadIdx.x < 32) {
        int ln = threadIdx.x;
        int c = (ln < 27) ? g_cnt[ln * 32] : 0;
        int tiles = (c + 31) >> 5;
        int incl = tiles;
#pragma unroll
        for (int o = 1; o < 32; o <<= 1) {
            int v = __shfl_up_sync(FULLMASK, incl, o);
            if (ln >= o) incl += v;
        }
        if (ln < 27) g_tilebase[ln] = incl - tiles;
        if (ln == 31) g_tilebase[27] = incl;
    }
}

// ---------------- sparse tap-sorted conv, software-pipelined ----------------
__global__ __launch_bounds__(CONV_THREADS, 1)
void k_conv_s(const float* __restrict__ in_feat, const float* __restrict__ kern) {
    extern __shared__ float s[];
    int* s_tb  = (int*)s;        // 28
    int* s_cnt = s_tb + 28;      // 27
    float* sw  = s + 64;
    int tid = threadIdx.x;
    if (tid < 28) s_tb[tid] = g_tilebase[tid];
    else if (tid < 55) s_cnt[tid - 28] = g_cnt[(tid - 28) * 32];
    // interleave weights: (t,ci,co) -> t*1024 + (ci>>1)*64 + ((co>>1)&3)*16 + (co>>3)*4 + (co&1)*2 + (ci&1)
    for (int i = tid; i < WFLOATS; i += CONV_THREADS) {
        int t = i >> 10, r = i & 1023;
        int ci = r >> 5, co = r & 31;
        int dst = (t << 10) | ((ci >> 1) << 6) | (((co >> 1) & 3) << 4) | ((co >> 3) << 2) | ((co & 1) << 1) | (ci & 1);
        sw[dst] = kern[i];
    }
    __syncthreads();

    int lane = tid & 31;
    int wloc = tid >> 5;
    float* stage = s + 64 + WFLOATS + wloc * (32 * PITCH);
    int warp  = blockIdx.x * CONV_WARPS + wloc;
    int nwarp = gridDim.x * CONV_WARPS;
    int total = s_tb[27];
    int pg = lane >> 2, cg = lane & 3;
    int grow = (lane >> 3);          // gather row subgroup 0..3
    int gcol = (lane & 7);           // gather column 0..7

    int T = warp;
    int t = 0, li = 0, cnt = 0;      unsigned pw = 0;
    int t2 = 0, li2 = 0, cnt2 = 0;   unsigned pw2 = 0;
    float4 G[8];

    if (T < total) {
        while (t < 26 && T >= s_tb[t + 1]) t++;
        li = T - s_tb[t]; cnt = s_cnt[t];
        int idx = (li << 5) + lane;
        pw = (idx < cnt) ? g_pairs[t * NMAX + idx] : 0u;
#pragma unroll
        for (int i = 0; i < 8; i++) {
            unsigned pr = __shfl_sync(FULLMASK, pw, 4 * i + grow);
            G[i] = ((const float4*)(in_feat + (size_t)(pr >> 16) * CC))[gcol];
        }
        int Tn = T + nwarp;
        if (Tn < total) {
            t2 = t;
            while (t2 < 26 && Tn >= s_tb[t2 + 1]) t2++;
            li2 = Tn - s_tb[t2]; cnt2 = s_cnt[t2];
            int idx2 = (li2 << 5) + lane;
            pw2 = (idx2 < cnt2) ? g_pairs[t2 * NMAX + idx2] : 0u;
        }
    }

    while (T < total) {
        __syncwarp();
        // stage current tile's gathered rows
#pragma unroll
        for (int i = 0; i < 8; i++)
            *(float4*)(stage + (4 * i + grow) * PITCH + gcol * 4) = G[i];
        __syncwarp();

        // kick off next tile's gather + depth-2 pair prefetch (hidden under compute)
        int Tn = T + nwarp;
        int t3 = t2, li3 = 0, cnt3 = 0; unsigned pw3 = 0;
        if (Tn < total) {
#pragma unroll
            for (int i = 0; i < 8; i++) {
                unsigned pr = __shfl_sync(FULLMASK, pw2, 4 * i + grow);
                G[i] = ((const float4*)(in_feat + (size_t)(pr >> 16) * CC))[gcol];
            }
            int Tnn = Tn + nwarp;
            if (Tnn < total) {
                while (t3 < 26 && Tnn >= s_tb[t3 + 1]) t3++;
                li3 = Tnn - s_tb[t3]; cnt3 = s_cnt[t3];
                int idx3 = (li3 << 5) + lane;
                pw3 = (idx3 < cnt3) ? g_pairs[t3 * NMAX + idx3] : 0u;
            }
        }

        // ---- compute tile T (tap t) ----
        unsigned long long acc[4][8];
#pragma unroll
        for (int k = 0; k < 4; k++)
#pragma unroll
            for (int j = 0; j < 8; j++) acc[k][j] = 0ull;

        const float* Wb = sw + (t << 10);
#pragma unroll
        for (int cp2 = 0; cp2 < 8; cp2++) {
            unsigned long long fx[4], fy[4];
#pragma unroll
            for (int k = 0; k < 4; k++) {
                double2 f = *(const double2*)(stage + (pg + 8 * k) * PITCH + cp2 * 4);
                fx[k] = __double_as_longlong(f.x);
                fy[k] = __double_as_longlong(f.y);
            }
#pragma unroll
            for (int h = 0; h < 2; h++) {
                const float* wr = Wb + (2 * cp2 + h) * 64 + cg * 4;
                double2 w0 = *(const double2*)(wr);
                double2 w1 = *(const double2*)(wr + 16);
                double2 w2 = *(const double2*)(wr + 32);
                double2 w3 = *(const double2*)(wr + 48);
                unsigned long long q0 = __double_as_longlong(w0.x);
                unsigned long long q1 = __double_as_longlong(w0.y);
                unsigned long long q2 = __double_as_longlong(w1.x);
                unsigned long long q3 = __double_as_longlong(w1.y);
                unsigned long long q4 = __double_as_longlong(w2.x);
                unsigned long long q5 = __double_as_longlong(w2.y);
                unsigned long long q6 = __double_as_longlong(w3.x);
                unsigned long long q7 = __double_as_longlong(w3.y);
#pragma unroll
                for (int k = 0; k < 4; k++) {
                    unsigned long long f2 = h ? fy[k] : fx[k];
                    acc[k][0] = fma2(f2, q0, acc[k][0]);
                    acc[k][1] = fma2(f2, q1, acc[k][1]);
                    acc[k][2] = fma2(f2, q2, acc[k][2]);
                    acc[k][3] = fma2(f2, q3, acc[k][3]);
                    acc[k][4] = fma2(f2, q4, acc[k][4]);
                    acc[k][5] = fma2(f2, q5, acc[k][5]);
                    acc[k][6] = fma2(f2, q6, acc[k][6]);
                    acc[k][7] = fma2(f2, q7, acc[k][7]);
                }
            }
        }

        // ---- scatter tile T ----
#pragma unroll
        for (int k = 0; k < 4; k++) {
            int j = pg + 8 * k;
            unsigned prj = __shfl_sync(FULLMASK, pw, j);
            if (((li << 5) + j) < cnt) {
                unsigned mrow = prj & 0xffffu;
                float* p = g_acc + (size_t)mrow * CC + cg * 8;
                red2(p,     hsum2(acc[k][0]), hsum2(acc[k][1]));
                red2(p + 2, hsum2(acc[k][2]), hsum2(acc[k][3]));
                red2(p + 4, hsum2(acc[k][4]), hsum2(acc[k][5]));
                red2(p + 6, hsum2(acc[k][6]), hsum2(acc[k][7]));
            }
        }

        // rotate pipeline
        T = Tn;
        t = t2; li = li2; cnt = cnt2; pw = pw2;
        t2 = t3; li2 = li3; cnt2 = cnt3; pw2 = pw3;
    }
}

// ---------------- epilogue ----------------
__global__ void k_epi(const float* __restrict__ mask, const float* __restrict__ bias,
                      const float* __restrict__ resid, float* __restrict__ outp,
                      int N, int do_relu, int reset) {
    int i = blockIdx.x * blockDim.x + threadIdx.x;
    if (i >= N * 8) return;
    int m = i >> 3, q = i & 7;
    float4 a = ((float4*)g_acc)[i];
    float mk = mask[m];
    float4 b = ((const float4*)bias)[q];
    float4 o;
    o.x = (a.x + mk * b.x) * mk;
    o.y = (a.y + mk * b.y) * mk;
    o.z = (a.z + mk * b.z) * mk;
    o.w = (a.w + mk * b.w) * mk;
    if (do_relu) {
        o.x = fmaxf(o.x, 0.f); o.y = fmaxf(o.y, 0.f);
        o.z = fmaxf(o.z, 0.f); o.w = fmaxf(o.w, 0.f);
    }
    if (resid) {
        float4 r = ((const float4*)resid)[i];
        o.x += r.x; o.y += r.y; o.z += r.z; o.w += r.w;
    }
    ((float4*)outp)[i] = o;
    if (reset) ((float4*)g_acc)[i] = make_float4(0.f, 0.f, 0.f, 0.f);
}

// ---------------- launch ----------------
extern "C" void kernel_launch(void* const* d_in, const int* in_sizes, int n_in,
                              void* d_out, int out_size)
{
    const float* values = (const float*)d_in[0];
    const void*  indices = d_in[1];
    const float* mask   = (const float*)d_in[2];
    const float* kern1  = (const float*)d_in[3];
    const float* bias1  = (const float*)d_in[4];
    const float* kern2  = (const float*)d_in[5];
    const float* bias2  = (const float*)d_in[6];
    float* out = (float*)d_out;

    int N = in_sizes[0] / CC;
    if (N > NMAX) N = NMAX;

    int smem = (64 + WFLOATS + CONV_WARPS * 32 * PITCH) * 4;   // 166144 B
    static int smem_set = 0;
    if (!smem_set) {
        cudaFuncSetAttribute(k_conv_s, cudaFuncAttributeMaxDynamicSharedMemorySize, smem);
        smem_set = 1;
    }

    float* h1;
    cudaGetSymbolAddress((void**)&h1, g_h1);

    k_pre<<<1024, 512>>>((const int*)indices);
    k_fill<<<(N + 255) / 256, 256>>>(indices, N);
    k_pairs<<<(N + 255) / 256, 256>>>(N);

    k_conv_s<<<148, CONV_THREADS, smem>>>(values, kern1);
    k_epi<<<(N * 8 + 511) / 512, 512>>>(mask, bias1, nullptr, h1, N, 1, 1);
    k_conv_s<<<148, CONV_THREADS, smem>>>(h1, kern2);
    k_epi<<<(N * 8 + 511) / 512, 512>>>(mask, bias2, values, out, N, 0, 0);
}

// round 6
// speedup vs baseline: 2.8915x; 1.2513x over previous
#include <cuda_runtime.h>

#define DD   64
#define GSZ  (DD*DD*DD)
#define NMAX 65536
#define CC   32
#define PITCH 36
#define STAGEF (32 * PITCH)       // 1152 floats per buffer
#define FULLMASK 0xffffffffu
#define WFLOATS (27 * 1024)
#define CONV_WARPS 12
#define CONV_THREADS (CONV_WARPS * 32)

// ---------------- device scratch ----------------
__device__ int   g_is64;
__device__ int   g_done;
__device__ int   g_grid[GSZ];
__device__ int   g_coords[NMAX];
__device__ unsigned int g_pairs[27 * NMAX];  // bucket t at t*NMAX: (src<<16)|m
__device__ int   g_cnt[27 * 32];             // padded counters
__device__ int   g_tilebase[28];
__device__ float g_acc[NMAX * CC];           // zero at load; epilogues re-zero
__device__ float g_h1[NMAX * CC];

// ---------------- f32x2 / async helpers ----------------
__device__ __forceinline__ unsigned long long fma2(unsigned long long a,
                                                   unsigned long long b,
                                                   unsigned long long c) {
    unsigned long long d;
    asm("fma.rn.f32x2 %0, %1, %2, %3;" : "=l"(d) : "l"(a), "l"(b), "l"(c));
    return d;
}
__device__ __forceinline__ float hsum2(unsigned long long a) {
    float lo, hi;
    asm("mov.b64 {%0, %1}, %2;" : "=f"(lo), "=f"(hi) : "l"(a));
    return lo + hi;
}
__device__ __forceinline__ void red4(float* p, float a, float b, float c, float d) {
    asm volatile("red.global.add.v4.f32 [%0], {%1, %2, %3, %4};"
                 :: "l"(p), "f"(a), "f"(b), "f"(c), "f"(d) : "memory");
}
__device__ __forceinline__ void cp16(float* smem_dst, const float4* gsrc) {
    unsigned dst = (unsigned)__cvta_generic_to_shared(smem_dst);
    asm volatile("cp.async.cg.shared.global [%0], [%1], 16;" :: "r"(dst), "l"(gsrc));
}
#define CP_COMMIT() asm volatile("cp.async.commit_group;" ::: "memory")
#define CP_WAIT1()  asm volatile("cp.async.wait_group 1;" ::: "memory")

// ---------------- pre: init + dtype detection ----------------
__global__ void k_pre(const int* __restrict__ idx32) {
    int i = blockIdx.x * blockDim.x + threadIdx.x;   // GSZ threads
    g_grid[i] = -1;
    if (i < 27 * 32) g_cnt[i] = 0;
    if (i == 0) g_done = 0;
    if (blockIdx.x == 0) {
        int v = (threadIdx.x < 256) ? idx32[2 * threadIdx.x + 1] : 0;
        int any = __syncthreads_count(v != 0);
        if (threadIdx.x == 0) g_is64 = (any == 0) ? 1 : 0;
    }
}

__global__ void k_fill(const void* __restrict__ idx, int N) {
    int m = blockIdx.x * blockDim.x + threadIdx.x;
    if (m >= N) return;
    int z, y, x;
    if (g_is64) {
        const long long* p = (const long long*)idx;
        z = (int)p[m * 4 + 1]; y = (int)p[m * 4 + 2]; x = (int)p[m * 4 + 3];
    } else {
        const int* p = (const int*)idx;
        z = p[m * 4 + 1]; y = p[m * 4 + 2]; x = p[m * 4 + 3];
    }
    int cp = (z << 12) | (y << 6) | x;
    g_coords[m] = cp;
    g_grid[cp] = m;
}

// Enumerate present (tap, src) per point, bucket by tap; last block does prefix.
__global__ void k_pairs(int N) {
    int m = blockIdx.x * blockDim.x + threadIdx.x;
    bool active = (m < N);
    int cp = active ? g_coords[m] : 0;
    int vv[3] = { (cp >> 12) & 63, (cp >> 6) & 63, cp & 63 };
    bool inter = true;
    int ti[3][3], sv[3][3];
#pragma unroll
    for (int a = 0; a < 3; a++) {
        int v = vv[a];
        if (v == 0) {
            inter = false;
            ti[a][0] = 0; sv[a][0] = 0;
            ti[a][1] = 0; sv[a][1] = 1;
            ti[a][2] = 1; sv[a][2] = 0;
        } else if (v == DD - 1) {
            inter = false;
            ti[a][0] = 2; sv[a][0] = DD - 2;
            ti[a][1] = 2; sv[a][1] = DD - 1;
            ti[a][2] = 1; sv[a][2] = DD - 1;
        } else {
            ti[a][0] = 0; sv[a][0] = v + 1;
            ti[a][1] = 1; sv[a][1] = v;
            ti[a][2] = 2; sv[a][2] = v - 1;
        }
    }
    int lane = threadIdx.x & 31;
    int slot = 0;
#pragma unroll
    for (int a = 0; a < 3; a++)
#pragma unroll
        for (int b = 0; b < 3; b++)
#pragma unroll
            for (int c = 0; c < 3; c++) {
                int t   = ti[0][a] * 9 + ti[1][b] * 3 + ti[2][c];
                int lin = (sv[0][a] << 12) | (sv[1][b] << 6) | sv[2][c];
                int src = active ? g_grid[lin] : -1;
                bool present = (src >= 0);
                bool fast = inter && present;   // here t == slot
                unsigned bal = __ballot_sync(FULLMASK, fast);
                int ldr = bal ? (__ffs(bal) - 1) : 0;
                int base = 0;
                if (bal && lane == ldr) base = atomicAdd(&g_cnt[slot * 32], __popc(bal));
                base = __shfl_sync(FULLMASK, base, ldr);
                int pos = 0;
                if (fast)          pos = base + __popc(bal & ((1u << lane) - 1u));
                else if (present)  pos = atomicAdd(&g_cnt[t * 32], 1);
                if (present) g_pairs[t * NMAX + pos] = ((unsigned)src << 16) | (unsigned)m;
                slot++;
            }

    // fused prefix sum: last block computes tile bases
    __shared__ int s_last;
    __threadfence();
    __syncthreads();
    if (threadIdx.x == 0)
        s_last = (atomicAdd(&g_done, 1) == (int)gridDim.x - 1) ? 1 : 0;
    __syncthreads();
    if (s_last && threadIdx.x < 32) {
        int ln = threadIdx.x;
        int c = (ln < 27) ? g_cnt[ln * 32] : 0;
        int tiles = (c + 31) >> 5;
        int incl = tiles;
#pragma unroll
        for (int o = 1; o < 32; o <<= 1) {
            int v = __shfl_up_sync(FULLMASK, incl, o);
            if (ln >= o) incl += v;
        }
        if (ln < 27) g_tilebase[ln] = incl - tiles;
        if (ln == 31) g_tilebase[27] = incl;
    }
}

// ---------------- sparse tap-sorted conv, cp.async double-buffered ----------------
__global__ __launch_bounds__(CONV_THREADS, 1)
void k_conv_s(const float* __restrict__ in_feat, const float* __restrict__ kern) {
    extern __shared__ float s[];
    int* s_tb  = (int*)s;        // 28
    int* s_cnt = s_tb + 28;      // 27
    float* sw  = s + 64;
    int tid = threadIdx.x;
    if (tid < 28) s_tb[tid] = g_tilebase[tid];
    else if (tid < 55) s_cnt[tid - 28] = g_cnt[(tid - 28) * 32];
    // interleave weights: (t,ci,co) -> t*1024 + (ci>>1)*64 + ((co>>1)&3)*16 + (co>>3)*4 + (co&1)*2 + (ci&1)
    for (int i = tid; i < WFLOATS; i += CONV_THREADS) {
        int t = i >> 10, r = i & 1023;
        int ci = r >> 5, co = r & 31;
        int dst = (t << 10) | ((ci >> 1) << 6) | (((co >> 1) & 3) << 4) | ((co >> 3) << 2) | ((co & 1) << 1) | (ci & 1);
        sw[dst] = kern[i];
    }
    __syncthreads();

    int lane = tid & 31;
    int wloc = tid >> 5;
    float* buf0 = s + 64 + WFLOATS + wloc * (2 * STAGEF);
    float* buf1 = buf0 + STAGEF;
    int warp  = blockIdx.x * CONV_WARPS + wloc;
    int nwarp = gridDim.x * CONV_WARPS;
    int total = s_tb[27];
    int pg = lane >> 2, cg = lane & 3;
    int grow = (lane >> 3);          // gather row subgroup 0..3
    int gcol = (lane & 7);           // gather column 0..7

    int T = warp;
    int t = 0, li = 0, cnt = 0;      unsigned pw = 0;    // tile T
    int t2 = 0, li2 = 0, cnt2 = 0;   unsigned pw2 = 0;   // tile T+nwarp
    int cur = 0;

    if (T < total) {
        while (t < 26 && T >= s_tb[t + 1]) t++;
        li = T - s_tb[t]; cnt = s_cnt[t];
        int idx = (li << 5) + lane;
        pw = (idx < cnt) ? g_pairs[t * NMAX + idx] : 0u;
        // async gather tile T into buf0
#pragma unroll
        for (int i = 0; i < 8; i++) {
            unsigned pr = __shfl_sync(FULLMASK, pw, 4 * i + grow);
            cp16(buf0 + (4 * i + grow) * PITCH + gcol * 4,
                 (const float4*)(in_feat + (size_t)(pr >> 16) * CC) + gcol);
        }
        CP_COMMIT();
        int Tn = T + nwarp;
        if (Tn < total) {
            t2 = t;
            while (t2 < 26 && Tn >= s_tb[t2 + 1]) t2++;
            li2 = Tn - s_tb[t2]; cnt2 = s_cnt[t2];
            int idx2 = (li2 << 5) + lane;
            pw2 = (idx2 < cnt2) ? g_pairs[t2 * NMAX + idx2] : 0u;
        }
    }

    while (T < total) {
        int Tn = T + nwarp;
        // async gather tile T+1 into the other buffer (empty commit keeps count)
        if (Tn < total) {
            float* nb = cur ? buf0 : buf1;
#pragma unroll
            for (int i = 0; i < 8; i++) {
                unsigned pr = __shfl_sync(FULLMASK, pw2, 4 * i + grow);
                cp16(nb + (4 * i + grow) * PITCH + gcol * 4,
                     (const float4*)(in_feat + (size_t)(pr >> 16) * CC) + gcol);
            }
        }
        CP_COMMIT();

        // prefetch tile T+2 metadata
        int t3 = t2, li3 = 0, cnt3 = 0; unsigned pw3 = 0;
        int Tnn = Tn + nwarp;
        if (Tnn < total) {
            while (t3 < 26 && Tnn >= s_tb[t3 + 1]) t3++;
            li3 = Tnn - s_tb[t3]; cnt3 = s_cnt[t3];
            int idx3 = (li3 << 5) + lane;
            pw3 = (idx3 < cnt3) ? g_pairs[t3 * NMAX + idx3] : 0u;
        }

        // wait for tile T's gather (T+1's may still be in flight)
        CP_WAIT1();
        __syncwarp();
        float* stage = cur ? buf1 : buf0;

        // ---- compute tile T (tap t) ----
        unsigned long long acc[4][8];
#pragma unroll
        for (int k = 0; k < 4; k++)
#pragma unroll
            for (int j = 0; j < 8; j++) acc[k][j] = 0ull;

        const float* Wb = sw + (t << 10);
#pragma unroll
        for (int cp2 = 0; cp2 < 8; cp2++) {
            unsigned long long fx[4], fy[4];
#pragma unroll
            for (int k = 0; k < 4; k++) {
                double2 f = *(const double2*)(stage + (pg + 8 * k) * PITCH + cp2 * 4);
                fx[k] = __double_as_longlong(f.x);
                fy[k] = __double_as_longlong(f.y);
            }
#pragma unroll
            for (int h = 0; h < 2; h++) {
                const float* wr = Wb + (2 * cp2 + h) * 64 + cg * 4;
                double2 w0 = *(const double2*)(wr);
                double2 w1 = *(const double2*)(wr + 16);
                double2 w2 = *(const double2*)(wr + 32);
                double2 w3 = *(const double2*)(wr + 48);
                unsigned long long q0 = __double_as_longlong(w0.x);
                unsigned long long q1 = __double_as_longlong(w0.y);
                unsigned long long q2 = __double_as_longlong(w1.x);
                unsigned long long q3 = __double_as_longlong(w1.y);
                unsigned long long q4 = __double_as_longlong(w2.x);
                unsigned long long q5 = __double_as_longlong(w2.y);
                unsigned long long q6 = __double_as_longlong(w3.x);
                unsigned long long q7 = __double_as_longlong(w3.y);
#pragma unroll
                for (int k = 0; k < 4; k++) {
                    unsigned long long f2 = h ? fy[k] : fx[k];
                    acc[k][0] = fma2(f2, q0, acc[k][0]);
                    acc[k][1] = fma2(f2, q1, acc[k][1]);
                    acc[k][2] = fma2(f2, q2, acc[k][2]);
                    acc[k][3] = fma2(f2, q3, acc[k][3]);
                    acc[k][4] = fma2(f2, q4, acc[k][4]);
                    acc[k][5] = fma2(f2, q5, acc[k][5]);
                    acc[k][6] = fma2(f2, q6, acc[k][6]);
                    acc[k][7] = fma2(f2, q7, acc[k][7]);
                }
            }
        }

        // ---- scatter tile T (v4 reductions) ----
#pragma unroll
        for (int k = 0; k < 4; k++) {
            int j = pg + 8 * k;
            unsigned prj = __shfl_sync(FULLMASK, pw, j);
            if (((li << 5) + j) < cnt) {
                unsigned mrow = prj & 0xffffu;
                float* p = g_acc + (size_t)mrow * CC + cg * 8;
                red4(p,     hsum2(acc[k][0]), hsum2(acc[k][1]),
                            hsum2(acc[k][2]), hsum2(acc[k][3]));
                red4(p + 4, hsum2(acc[k][4]), hsum2(acc[k][5]),
                            hsum2(acc[k][6]), hsum2(acc[k][7]));
            }
        }

        // rotate pipeline
        T = Tn; cur ^= 1;
        t = t2; li = li2; cnt = cnt2; pw = pw2;
        t2 = t3; li2 = li3; cnt2 = cnt3; pw2 = pw3;
    }
}

// ---------------- epilogue (always resets g_acc behind itself) ----------------
__global__ void k_epi(const float* __restrict__ mask, const float* __restrict__ bias,
                      const float* __restrict__ resid, float* __restrict__ outp,
                      int N, int do_relu) {
    int i = blockIdx.x * blockDim.x + threadIdx.x;
    if (i >= N * 8) return;
    int m = i >> 3, q = i & 7;
    float4 a = ((float4*)g_acc)[i];
    float mk = mask[m];
    float4 b = ((const float4*)bias)[q];
    float4 o;
    o.x = (a.x + mk * b.x) * mk;
    o.y = (a.y + mk * b.y) * mk;
    o.z = (a.z + mk * b.z) * mk;
    o.w = (a.w + mk * b.w) * mk;
    if (do_relu) {
        o.x = fmaxf(o.x, 0.f); o.y = fmaxf(o.y, 0.f);
        o.z = fmaxf(o.z, 0.f); o.w = fmaxf(o.w, 0.f);
    }
    if (resid) {
        float4 r = ((const float4*)resid)[i];
        o.x += r.x; o.y += r.y; o.z += r.z; o.w += r.w;
    }
    ((float4*)outp)[i] = o;
    ((float4*)g_acc)[i] = make_float4(0.f, 0.f, 0.f, 0.f);
}

// ---------------- launch ----------------
extern "C" void kernel_launch(void* const* d_in, const int* in_sizes, int n_in,
                              void* d_out, int out_size)
{
    const float* values = (const float*)d_in[0];
    const void*  indices = d_in[1];
    const float* mask   = (const float*)d_in[2];
    const float* kern1  = (const float*)d_in[3];
    const float* bias1  = (const float*)d_in[4];
    const float* kern2  = (const float*)d_in[5];
    const float* bias2  = (const float*)d_in[6];
    float* out = (float*)d_out;

    int N = in_sizes[0] / CC;
    if (N > NMAX) N = NMAX;

    int smem = (64 + WFLOATS + CONV_WARPS * 2 * STAGEF) * 4;   // 221440 B
    static int smem_set = 0;
    if (!smem_set) {
        cudaFuncSetAttribute(k_conv_s, cudaFuncAttributeMaxDynamicSharedMemorySize, smem);
        smem_set = 1;
    }

    float* h1;
    cudaGetSymbolAddress((void**)&h1, g_h1);

    k_pre<<<GSZ / 512, 512>>>((const int*)indices);
    k_fill<<<(N + 255) / 256, 256>>>(indices, N);
    k_pairs<<<(N + 255) / 256, 256>>>(N);

    k_conv_s<<<148, CONV_THREADS, smem>>>(values, kern1);
    k_epi<<<(N * 8 + 511) / 512, 512>>>(mask, bias1, nullptr, h1, N, 1);
    k_conv_s<<<148, CONV_THREADS, smem>>>(h1, kern2);
    k_epi<<<(N * 8 + 511) / 512, 512>>>(mask, bias2, values, out, N, 0);
}

// round 7
// speedup vs baseline: 3.0029x; 1.0385x over previous
#include <cuda_runtime.h>

#define DD   64
#define GSZ  (DD*DD*DD)
#define NMAX 65536
#define CC   32
#define PITCH 36
#define STAGEF (32 * PITCH)       // 1152 floats per buffer
#define FULLMASK 0xffffffffu
#define GRIDB 148
#define THR   512
#define CONV_WARPS 16
#define NTAP_SEG 6

// ---------------- device scratch ----------------
__device__ int   g_is64;
__device__ int   g_done;
__device__ int   g_bar;                      // monotone ticket barrier counter
__device__ int   g_grid[GSZ];
__device__ int   g_coords[NMAX];
__device__ unsigned int g_pairs[27 * NMAX];  // bucket t at t*NMAX: (src<<16)|m
__device__ int   g_cnt[27 * 32];             // padded counters
__device__ int   g_tilebase[28];
__device__ float g_acc[NMAX * CC];           // zero at load; epilogues re-zero
__device__ float g_h1[NMAX * CC];

// ---------------- helpers ----------------
__device__ __forceinline__ unsigned long long fma2(unsigned long long a,
                                                   unsigned long long b,
                                                   unsigned long long c) {
    unsigned long long d;
    asm("fma.rn.f32x2 %0, %1, %2, %3;" : "=l"(d) : "l"(a), "l"(b), "l"(c));
    return d;
}
__device__ __forceinline__ float hsum2(unsigned long long a) {
    float lo, hi;
    asm("mov.b64 {%0, %1}, %2;" : "=f"(lo), "=f"(hi) : "l"(a));
    return lo + hi;
}
__device__ __forceinline__ void red4(float* p, float a, float b, float c, float d) {
    asm volatile("red.global.add.v4.f32 [%0], {%1, %2, %3, %4};"
                 :: "l"(p), "f"(a), "f"(b), "f"(c), "f"(d) : "memory");
}
__device__ __forceinline__ void cp16(float* smem_dst, const float4* gsrc) {
    unsigned dst = (unsigned)__cvta_generic_to_shared(smem_dst);
    asm volatile("cp.async.cg.shared.global [%0], [%1], 16;" :: "r"(dst), "l"(gsrc));
}
#define CP_COMMIT() asm volatile("cp.async.commit_group;" ::: "memory")
#define CP_WAIT1()  asm volatile("cp.async.wait_group 1;" ::: "memory")

// replay-safe grid barrier: ticket encodes which barrier instance this is
__device__ __forceinline__ void grid_barrier() {
    __syncthreads();
    if (threadIdx.x == 0) {
        __threadfence();
        int ticket = atomicAdd(&g_bar, 1);
        int target = (ticket / GRIDB + 1) * GRIDB;
        volatile int* vb = &g_bar;
        while (*vb < target) { }
    }
    __syncthreads();
}

// ---------------- fused prep: init -> fill -> pairs (+prefix) ----------------
__global__ __launch_bounds__(THR, 1)
void k_prep(const void* __restrict__ idx, int N) {
    int tid = threadIdx.x;
    int gt  = blockIdx.x * THR + tid;

    // ---- phase A: init ----
    for (int i = gt; i < GSZ; i += GRIDB * THR) g_grid[i] = -1;
    if (gt < 27 * 32) g_cnt[gt] = 0;
    if (gt == 0) g_done = 0;
    {
        int v = (blockIdx.x == 0 && tid < 256) ? ((const int*)idx)[2 * tid + 1] : 0;
        int any = __syncthreads_count(v != 0);
        if (blockIdx.x == 0 && tid == 0) g_is64 = (any == 0) ? 1 : 0;
    }
    grid_barrier();

    // ---- phase B: fill grid (single pass: N <= GRIDB*THR) ----
    int m = gt;
    if (m < N) {
        int z, y, x;
        if (g_is64) {
            const long long* p = (const long long*)idx;
            z = (int)p[m * 4 + 1]; y = (int)p[m * 4 + 2]; x = (int)p[m * 4 + 3];
        } else {
            const int* p = (const int*)idx;
            z = p[m * 4 + 1]; y = p[m * 4 + 2]; x = p[m * 4 + 3];
        }
        int cp = (z << 12) | (y << 6) | x;
        g_coords[m] = cp;
        g_grid[cp] = m;
    }
    grid_barrier();

    // ---- phase C: pairs ----
    bool active = (m < N);
    int cp = active ? g_coords[m] : 0;
    int vv[3] = { (cp >> 12) & 63, (cp >> 6) & 63, cp & 63 };
    bool inter = true;
    int ti[3][3], sv[3][3];
#pragma unroll
    for (int a = 0; a < 3; a++) {
        int v = vv[a];
        if (v == 0) {
            inter = false;
            ti[a][0] = 0; sv[a][0] = 0;
            ti[a][1] = 0; sv[a][1] = 1;
            ti[a][2] = 1; sv[a][2] = 0;
        } else if (v == DD - 1) {
            inter = false;
            ti[a][0] = 2; sv[a][0] = DD - 2;
            ti[a][1] = 2; sv[a][1] = DD - 1;
            ti[a][2] = 1; sv[a][2] = DD - 1;
        } else {
            ti[a][0] = 0; sv[a][0] = v + 1;
            ti[a][1] = 1; sv[a][1] = v;
            ti[a][2] = 2; sv[a][2] = v - 1;
        }
    }
    int lane = tid & 31;
    int slot = 0;
#pragma unroll
    for (int a = 0; a < 3; a++)
#pragma unroll
        for (int b = 0; b < 3; b++)
#pragma unroll
            for (int c = 0; c < 3; c++) {
                int t   = ti[0][a] * 9 + ti[1][b] * 3 + ti[2][c];
                int lin = (sv[0][a] << 12) | (sv[1][b] << 6) | sv[2][c];
                int src = active ? g_grid[lin] : -1;
                bool present = (src >= 0);
                bool fast = inter && present;   // here t == slot
                unsigned bal = __ballot_sync(FULLMASK, fast);
                int ldr = bal ? (__ffs(bal) - 1) : 0;
                int base = 0;
                if (bal && lane == ldr) base = atomicAdd(&g_cnt[slot * 32], __popc(bal));
                base = __shfl_sync(FULLMASK, base, ldr);
                int pos = 0;
                if (fast)          pos = base + __popc(bal & ((1u << lane) - 1u));
                else if (present)  pos = atomicAdd(&g_cnt[t * 32], 1);
                if (present) g_pairs[t * NMAX + pos] = ((unsigned)src << 16) | (unsigned)m;
                slot++;
            }

    // last block computes tile-base prefix sum
    __shared__ int s_last;
    __threadfence();
    __syncthreads();
    if (tid == 0)
        s_last = (atomicAdd(&g_done, 1) == GRIDB - 1) ? 1 : 0;
    __syncthreads();
    if (s_last && tid < 32) {
        int ln = tid;
        int c = (ln < 27) ? g_cnt[ln * 32] : 0;
        int tiles = (c + 31) >> 5;
        int incl = tiles;
#pragma unroll
        for (int o = 1; o < 32; o <<= 1) {
            int v = __shfl_up_sync(FULLMASK, incl, o);
            if (ln >= o) incl += v;
        }
        if (ln < 27) g_tilebase[ln] = incl - tiles;
        if (ln == 31) g_tilebase[27] = incl;
    }
}

// ---------------- sparse tap-sorted conv: contiguous chunks, 16 warps ----------------
__global__ __launch_bounds__(THR, 1)
void k_conv_s(const float* __restrict__ in_feat, const float* __restrict__ kern) {
    extern __shared__ float s[];
    int* s_tb  = (int*)s;        // 28
    int* s_cnt = s_tb + 28;      // 27
    float* sw  = s + 64;         // NTAP_SEG * 1024 floats
    int tid = threadIdx.x;
    if (tid < 28) s_tb[tid] = g_tilebase[tid];
    else if (tid < 55) s_cnt[tid - 28] = g_cnt[(tid - 28) * 32];
    __syncthreads();

    int total = s_tb[27];
    int c0 = (int)(((long long)total * blockIdx.x) / GRIDB);
    int c1 = (int)(((long long)total * (blockIdx.x + 1)) / GRIDB);
    if (c0 >= c1) return;

    int t_lo = 0;
    while (t_lo < 26 && c0 >= s_tb[t_lo + 1]) t_lo++;
    int t_hi = t_lo;
    while (t_hi < 26 && (c1 - 1) >= s_tb[t_hi + 1]) t_hi++;

    int lane = tid & 31;
    int wloc = tid >> 5;
    float* buf0 = s + 64 + NTAP_SEG * 1024 + wloc * (2 * STAGEF);
    float* buf1 = buf0 + STAGEF;
    int pg = lane >> 2, cg = lane & 3;
    int grow = (lane >> 3);
    int gcol = (lane & 7);

    for (int seg = t_lo; seg <= t_hi; seg += NTAP_SEG) {
        int segHi = min(seg + NTAP_SEG - 1, t_hi);
        __syncthreads();
        // load weights for taps [seg, segHi], interleaved:
        // (tr,ci,co) -> tr*1024 + (ci>>1)*64 + ((co>>1)&3)*16 + (co>>3)*4 + (co&1)*2 + (ci&1)
        int nelem = (segHi - seg + 1) << 10;
        for (int i = tid; i < nelem; i += THR) {
            int tr = i >> 10, r = i & 1023;
            int ci = r >> 5, co = r & 31;
            int dst = (tr << 10) | ((ci >> 1) << 6) | (((co >> 1) & 3) << 4) |
                      ((co >> 3) << 2) | ((co & 1) << 1) | (ci & 1);
            sw[dst] = kern[((seg + tr) << 10) + r];
        }
        __syncthreads();

        int r0 = max(c0, s_tb[seg]);
        int r1 = min(c1, s_tb[segHi + 1]);

        int T = r0 + wloc;
        int t = seg, li = 0, cnt = 0;   unsigned pw = 0;
        int t2 = seg, li2 = 0, cnt2 = 0; unsigned pw2 = 0;
        int cur = 0;

        if (T < r1) {
            while (t < segHi && T >= s_tb[t + 1]) t++;
            li = T - s_tb[t]; cnt = s_cnt[t];
            int idx = (li << 5) + lane;
            pw = (idx < cnt) ? g_pairs[t * NMAX + idx] : 0u;
#pragma unroll
            for (int i = 0; i < 8; i++) {
                unsigned pr = __shfl_sync(FULLMASK, pw, 4 * i + grow);
                cp16(buf0 + (4 * i + grow) * PITCH + gcol * 4,
                     (const float4*)(in_feat + (size_t)(pr >> 16) * CC) + gcol);
            }
            CP_COMMIT();
            int Tn = T + CONV_WARPS;
            if (Tn < r1) {
                t2 = t;
                while (t2 < segHi && Tn >= s_tb[t2 + 1]) t2++;
                li2 = Tn - s_tb[t2]; cnt2 = s_cnt[t2];
                int idx2 = (li2 << 5) + lane;
                pw2 = (idx2 < cnt2) ? g_pairs[t2 * NMAX + idx2] : 0u;
            }
        }

        while (T < r1) {
            int Tn = T + CONV_WARPS;
            if (Tn < r1) {
                float* nb = cur ? buf0 : buf1;
#pragma unroll
                for (int i = 0; i < 8; i++) {
                    unsigned pr = __shfl_sync(FULLMASK, pw2, 4 * i + grow);
                    cp16(nb + (4 * i + grow) * PITCH + gcol * 4,
                         (const float4*)(in_feat + (size_t)(pr >> 16) * CC) + gcol);
                }
            }
            CP_COMMIT();

            // prefetch T+2 metadata
            int t3 = t2, li3 = 0, cnt3 = 0; unsigned pw3 = 0;
            int Tnn = Tn + CONV_WARPS;
            if (Tnn < r1) {
                while (t3 < segHi && Tnn >= s_tb[t3 + 1]) t3++;
                li3 = Tnn - s_tb[t3]; cnt3 = s_cnt[t3];
                int idx3 = (li3 << 5) + lane;
                pw3 = (idx3 < cnt3) ? g_pairs[t3 * NMAX + idx3] : 0u;
            }

            CP_WAIT1();
            __syncwarp();
            float* stage = cur ? buf1 : buf0;

            // ---- compute tile T (tap t) ----
            unsigned long long acc[4][8];
#pragma unroll
            for (int k = 0; k < 4; k++)
#pragma unroll
                for (int j = 0; j < 8; j++) acc[k][j] = 0ull;

            const float* Wb = sw + ((t - seg) << 10);
#pragma unroll
            for (int cp2 = 0; cp2 < 8; cp2++) {
                unsigned long long fx[4], fy[4];
#pragma unroll
                for (int k = 0; k < 4; k++) {
                    double2 f = *(const double2*)(stage + (pg + 8 * k) * PITCH + cp2 * 4);
                    fx[k] = __double_as_longlong(f.x);
                    fy[k] = __double_as_longlong(f.y);
                }
#pragma unroll
                for (int h = 0; h < 2; h++) {
                    const float* wr = Wb + (2 * cp2 + h) * 64 + cg * 4;
                    double2 w0 = *(const double2*)(wr);
                    double2 w1 = *(const double2*)(wr + 16);
                    double2 w2 = *(const double2*)(wr + 32);
                    double2 w3 = *(const double2*)(wr + 48);
                    unsigned long long q0 = __double_as_longlong(w0.x);
                    unsigned long long q1 = __double_as_longlong(w0.y);
                    unsigned long long q2 = __double_as_longlong(w1.x);
                    unsigned long long q3 = __double_as_longlong(w1.y);
                    unsigned long long q4 = __double_as_longlong(w2.x);
                    unsigned long long q5 = __double_as_longlong(w2.y);
                    unsigned long long q6 = __double_as_longlong(w3.x);
                    unsigned long long q7 = __double_as_longlong(w3.y);
#pragma unroll
                    for (int k = 0; k < 4; k++) {
                        unsigned long long f2 = h ? fy[k] : fx[k];
                        acc[k][0] = fma2(f2, q0, acc[k][0]);
                        acc[k][1] = fma2(f2, q1, acc[k][1]);
                        acc[k][2] = fma2(f2, q2, acc[k][2]);
                        acc[k][3] = fma2(f2, q3, acc[k][3]);
                        acc[k][4] = fma2(f2, q4, acc[k][4]);
                        acc[k][5] = fma2(f2, q5, acc[k][5]);
                        acc[k][6] = fma2(f2, q6, acc[k][6]);
                        acc[k][7] = fma2(f2, q7, acc[k][7]);
                    }
                }
            }

            // ---- scatter tile T ----
#pragma unroll
            for (int k = 0; k < 4; k++) {
                int j = pg + 8 * k;
                unsigned prj = __shfl_sync(FULLMASK, pw, j);
                if (((li << 5) + j) < cnt) {
                    unsigned mrow = prj & 0xffffu;
                    float* p = g_acc + (size_t)mrow * CC + cg * 8;
                    red4(p,     hsum2(acc[k][0]), hsum2(acc[k][1]),
                                hsum2(acc[k][2]), hsum2(acc[k][3]));
                    red4(p + 4, hsum2(acc[k][4]), hsum2(acc[k][5]),
                                hsum2(acc[k][6]), hsum2(acc[k][7]));
                }
            }

            T = Tn; cur ^= 1;
            t = t2; li = li2; cnt = cnt2; pw = pw2;
            t2 = t3; li2 = li3; cnt2 = cnt3; pw2 = pw3;
        }
    }
}

// ---------------- epilogue (always resets g_acc behind itself) ----------------
__global__ void k_epi(const float* __restrict__ mask, const float* __restrict__ bias,
                      const float* __restrict__ resid, float* __restrict__ outp,
                      int N, int do_relu) {
    int i = blockIdx.x * blockDim.x + threadIdx.x;
    if (i >= N * 8) return;
    int m = i >> 3, q = i & 7;
    float4 a = ((float4*)g_acc)[i];
    float mk = mask[m];
    float4 b = ((const float4*)bias)[q];
    float4 o;
    o.x = (a.x + mk * b.x) * mk;
    o.y = (a.y + mk * b.y) * mk;
    o.z = (a.z + mk * b.z) * mk;
    o.w = (a.w + mk * b.w) * mk;
    if (do_relu) {
        o.x = fmaxf(o.x, 0.f); o.y = fmaxf(o.y, 0.f);
        o.z = fmaxf(o.z, 0.f); o.w = fmaxf(o.w, 0.f);
    }
    if (resid) {
        float4 r = ((const float4*)resid)[i];
        o.x += r.x; o.y += r.y; o.z += r.z; o.w += r.w;
    }
    ((float4*)outp)[i] = o;
    ((float4*)g_acc)[i] = make_float4(0.f, 0.f, 0.f, 0.f);
}

// ---------------- launch ----------------
extern "C" void kernel_launch(void* const* d_in, const int* in_sizes, int n_in,
                              void* d_out, int out_size)
{
    const float* values = (const float*)d_in[0];
    const void*  indices = d_in[1];
    const float* mask   = (const float*)d_in[2];
    const float* kern1  = (const float*)d_in[3];
    const float* bias1  = (const float*)d_in[4];
    const float* kern2  = (const float*)d_in[5];
    const float* bias2  = (const float*)d_in[6];
    float* out = (float*)d_out;

    int N = in_sizes[0] / CC;
    if (N > NMAX) N = NMAX;

    int smem = (64 + NTAP_SEG * 1024 + CONV_WARPS * 2 * STAGEF) * 4;   // 172288 B
    static int smem_set = 0;
    if (!smem_set) {
        cudaFuncSetAttribute(k_conv_s, cudaFuncAttributeMaxDynamicSharedMemorySize, smem);
        smem_set = 1;
    }

    float* h1;
    cudaGetSymbolAddress((void**)&h1, g_h1);

    k_prep<<<GRIDB, THR>>>(indices, N);
    k_conv_s<<<GRIDB, THR, smem>>>(values, kern1);
    k_epi<<<(N * 8 + 511) / 512, 512>>>(mask, bias1, nullptr, h1, N, 1);
    k_conv_s<<<GRIDB, THR, smem>>>(h1, kern2);
    k_epi<<<(N * 8 + 511) / 512, 512>>>(mask, bias2, values, out, N, 0);
}